// round 9
// baseline (speedup 1.0000x reference)
#include <cuda_runtime.h>
#include <stdint.h>

#define NLAYERS 24
#define BATCH   512
#define RDIM    32
#define LQ      256
#define LOUT    257
#define NROWS   (NLAYERS*BATCH*RDIM)      /* 393216 rows */
#define QOUT_ELEMS (NROWS*LOUT)           /* 101,056,512 */
#define QOUT4   (QOUT_ELEMS/4)            /* 25,264,128  */
#define TILE4   2048u                     /* float4 per tile = 32KB */
#define NTILES  12336u                    /* QOUT4 / TILE4, exact */
#define NCOMPUTE 64
#define NCOPYB   514                      /* 514*22 = 11308 tiles */
#define TPC      22                       /* tiles per copy block */
#define CTAIL    11308u                   /* first tile of compute-block share */
#define FULLMASK 0xffffffffu

// ---------------- scratch (static device globals; no allocation) ----------------
__device__ float2 g_wT [NLAYERS*32*128];   // [l][j][row] -> (w_past, w_h)
__device__ float  g_f1T[NLAYERS*32*128];   // [l][j][k]

__device__ __forceinline__ float sigf(float v) { return 1.0f / (1.0f + __expf(-v)); }

// ---------------- K0: weight transposes for coalesced lane access ----------------
__global__ void prep_kernel(const float* __restrict__ conv_w,
                            const float* __restrict__ fc1_w) {
    int idx = blockIdx.x * blockDim.x + threadIdx.x;
    if (idx >= NLAYERS * 32 * 128) return;
    {
        int l = idx / 4096, rem = idx & 4095, row = rem / 32, j = rem & 31;
        float2 v = ((const float2*)conv_w)[idx];
        g_wT[(l * 32 + j) * 128 + row] = v;
    }
    {
        int l = idx / 4096, rem = idx & 4095, j = rem >> 7, k = rem & 127;
        g_f1T[idx] = fc1_w[k * 768 + l * 32 + j];
        (void)l;
    }
}

// ---- one 2048-float4 tile; ILPB in-flight float4s per thread per batch --------
template <int ILPB>
__device__ __forceinline__ void copy_tile(const float* __restrict__ queues,
                                          float* __restrict__ out,
                                          unsigned tile, unsigned tid)
{
    float4* oq = (float4*)(out + BATCH);
    unsigned base0 = tile * TILE4;
    #pragma unroll
    for (int bb = 0; bb < 8 / ILPB; bb++) {
        unsigned base = base0 + (unsigned)bb * (ILPB * 256u);
        float4 v[ILPB];
        #pragma unroll
        for (int k = 0; k < ILPB; k++) {
            unsigned i4  = base + (unsigned)k * 256u + tid;
            unsigned e   = i4 * 4u;
            unsigned row = e / 257u;
            unsigned t   = e - row * 257u;
            if (t < 253u) {
                const float* src = queues + (size_t)row * 256u + t;
                v[k].x = __ldcs(src + 0);
                v[k].y = __ldcs(src + 1);
                v[k].z = __ldcs(src + 2);
                v[k].w = __ldcs(src + 3);
            }
        }
        #pragma unroll
        for (int k = 0; k < ILPB; k++) {
            unsigned i4  = base + (unsigned)k * 256u + tid;
            unsigned e   = i4 * 4u;
            unsigned row = e / 257u;
            unsigned t   = e - row * 257u;
            if (t < 253u) {
                __stcs(oq + i4, v[k]);
            } else {
                // row-wrap / t==256 slow path (t==256 owned by compute warps)
                #pragma unroll
                for (int j = 0; j < 4; j++) {
                    unsigned ee = e + (unsigned)j;
                    unsigned r2 = ee / 257u;
                    unsigned t2 = ee - r2 * 257u;
                    if (t2 < 256u) {
                        float val = __ldcs(queues + (size_t)r2 * 256u + t2);
                        __stcs(out + BATCH + ee, val);
                    }
                }
            }
        }
    }
}

// ---------------- K1: fused recurrence + perfectly scheduled copy ----------------
__global__ void __launch_bounds__(256, 4) main_kernel(
    const float* __restrict__ x,      const float* __restrict__ feat,
    const float* __restrict__ queues,
    const float* __restrict__ fc_h_w, const float* __restrict__ fc_h_b,
    const float* __restrict__ fc_c_w, const float* __restrict__ fc_c_b,
    const float* __restrict__ conv_b,
    const float* __restrict__ fc1_b,  const float* __restrict__ fc2_w,
    const float* __restrict__ fc2_b,
    float* __restrict__ out)
{
    unsigned tid = threadIdx.x;
    if (blockIdx.x < NCOMPUTE) {
        // ---- compute path: 1 warp = 1 batch element; lane = R index ----
        int warp = threadIdx.x >> 5;
        int lane = threadIdx.x & 31;
        int b    = blockIdx.x * 8 + warp;

        float h, c;
        {
            float ha = fc_h_b[lane], ca = fc_c_b[lane];
            #pragma unroll
            for (int i = 0; i < 9; i++) {
                float wh = fc_h_w[lane * 9 + i];
                float wc = fc_c_w[lane * 9 + i];
                float v  = (i == 0) ? x[b] : feat[b * 8 + i - 1];
                ha += wh * v; ca += wc * v;
            }
            h = tanhf(ha); c = tanhf(ca);
        }
        out[BATCH + (size_t)((0 * BATCH + b) * RDIM + lane) * LOUT + 256] = h;

        float y0 = 0.f, y1 = 0.f, y2 = 0.f, y3 = 0.f;

        #pragma unroll 1
        for (int l = 0; l < NLAYERS; l++) {
            int dil = 1 << (l & 7);
            float p = __ldg(queues + (size_t)((l * BATCH + b) * RDIM + lane) * LQ + (LQ - dil));

            float a0 = __ldg(conv_b + l * 128 +  0 + lane);
            float a1 = __ldg(conv_b + l * 128 + 32 + lane);
            float a2 = __ldg(conv_b + l * 128 + 64 + lane);
            float a3 = __ldg(conv_b + l * 128 + 96 + lane);

            const float2* wp = g_wT + l * 32 * 128;
            #pragma unroll 8
            for (int j = 0; j < 32; j++) {
                float pj = __shfl_sync(FULLMASK, p, j);
                float hj = __shfl_sync(FULLMASK, h, j);
                float2 w0 = wp[j * 128 +  0 + lane];
                float2 w1 = wp[j * 128 + 32 + lane];
                float2 w2 = wp[j * 128 + 64 + lane];
                float2 w3 = wp[j * 128 + 96 + lane];
                a0 += w0.x * pj + w0.y * hj;
                a1 += w1.x * pj + w1.y * hj;
                a2 += w2.x * pj + w2.y * hj;
                a3 += w3.x * pj + w3.y * hj;
            }
            c = sigf(a0) * c + tanhf(a1) * sigf(a2);
            h = sigf(a3) * tanhf(c);

            if (l < NLAYERS - 1)
                out[BATCH + (size_t)(((l + 1) * BATCH + b) * RDIM + lane) * LOUT + 256] = h;

            const float* f1p = g_f1T + l * 32 * 128;
            #pragma unroll 8
            for (int j = 0; j < 32; j++) {
                float hj = __shfl_sync(FULLMASK, h, j);
                y0 += f1p[j * 128 +  0 + lane] * hj;
                y1 += f1p[j * 128 + 32 + lane] * hj;
                y2 += f1p[j * 128 + 64 + lane] * hj;
                y3 += f1p[j * 128 + 96 + lane] * hj;
            }
        }

        float sacc = fmaxf(y0 + fc1_b[ 0 + lane], 0.f) * fc2_w[ 0 + lane]
                   + fmaxf(y1 + fc1_b[32 + lane], 0.f) * fc2_w[32 + lane]
                   + fmaxf(y2 + fc1_b[64 + lane], 0.f) * fc2_w[64 + lane]
                   + fmaxf(y3 + fc1_b[96 + lane], 0.f) * fc2_w[96 + lane];
        #pragma unroll
        for (int off = 16; off > 0; off >>= 1)
            sacc += __shfl_xor_sync(FULLMASK, sacc, off);
        if (lane == 0) out[b] = sacc + fc2_b[0];

        // ---- tail copy share: 16 tiles (17 for blocks 0-3), ILP=4 (reg-light) ----
        unsigned j2    = blockIdx.x;
        unsigned cnt   = 16u + (j2 < 4u);
        unsigned start = CTAIL + j2 * 16u + min(j2, 4u);
        for (unsigned ti = 0; ti < cnt; ti++)
            copy_tile<4>(queues, out, start + ti, tid);
    } else {
        // ---- copy path: exactly TPC tiles per block, one wave, no tail ----
        unsigned cb    = blockIdx.x - NCOMPUTE;
        unsigned start = cb * TPC;
        #pragma unroll 1
        for (unsigned ti = 0; ti < TPC; ti++)
            copy_tile<8>(queues, out, start + ti, tid);
    }
}

extern "C" void kernel_launch(void* const* d_in, const int* in_sizes, int n_in,
                              void* d_out, int out_size) {
    const float* x      = (const float*)d_in[0];
    const float* feat   = (const float*)d_in[1];
    const float* queues = (const float*)d_in[2];
    const float* fc_h_w = (const float*)d_in[3];
    const float* fc_h_b = (const float*)d_in[4];
    const float* fc_c_w = (const float*)d_in[5];
    const float* fc_c_b = (const float*)d_in[6];
    const float* conv_w = (const float*)d_in[7];
    const float* conv_b = (const float*)d_in[8];
    const float* fc1_w  = (const float*)d_in[9];
    const float* fc1_b  = (const float*)d_in[10];
    const float* fc2_w  = (const float*)d_in[11];
    const float* fc2_b  = (const float*)d_in[12];
    float* out = (float*)d_out;

    prep_kernel<<<(NLAYERS * 32 * 128 + 255) / 256, 256>>>(conv_w, fc1_w);
    main_kernel<<<NCOMPUTE + NCOPYB, 256>>>(x, feat, queues,
                                            fc_h_w, fc_h_b, fc_c_w, fc_c_b,
                                            conv_b, fc1_b, fc2_w, fc2_b, out);
}

// round 10
// speedup vs baseline: 1.1722x; 1.1722x over previous
#include <cuda_runtime.h>
#include <stdint.h>

#define NLAYERS 24
#define BATCH   512
#define RDIM    32
#define LQ      256
#define LOUT    257
#define NROWS   (NLAYERS*BATCH*RDIM)      /* 393216 rows */
#define QOUT_ELEMS (NROWS*LOUT)           /* 101,056,512 */
#define QOUT4   (QOUT_ELEMS/4)            /* 25,264,128  */
#define TILE4   2048u                     /* float4 per block-iteration = 32KB */
#define NCOMPUTE 64                       /* 64 blocks x 8 warps = 512 batches */
#define NCOPYB   2056                     /* 12336 tiles / 2056 = exactly 6 each */
#define ILP      8
#define FULLMASK 0xffffffffu

// ---------------- scratch (static device globals; no allocation) ----------------
__device__ float2 g_wT [NLAYERS*32*128];   // [l][j][row] -> (w_past, w_h)
__device__ float  g_f1T[NLAYERS*32*128];   // [l][j][k]
__device__ unsigned long long g_ctr = 0;   // generation barrier (monotonic)

__device__ __forceinline__ float sigf(float v) { return 1.0f / (1.0f + __expf(-v)); }

// ---------------- K1: fused prep + recurrence + queue copy ----------------------
__global__ void __launch_bounds__(256, 4) main_kernel(
    const float* __restrict__ x,      const float* __restrict__ feat,
    const float* __restrict__ queues,
    const float* __restrict__ fc_h_w, const float* __restrict__ fc_h_b,
    const float* __restrict__ fc_c_w, const float* __restrict__ fc_c_b,
    const float* __restrict__ conv_w, const float* __restrict__ conv_b,
    const float* __restrict__ fc1_w,
    const float* __restrict__ fc1_b,  const float* __restrict__ fc2_w,
    const float* __restrict__ fc2_b,
    float* __restrict__ out)
{
    if (blockIdx.x < NCOMPUTE) {
        // ---- prep: 64 blocks x 256 threads transpose weights (6 items each) ----
        {
            int base = blockIdx.x * 256 + threadIdx.x;
            #pragma unroll
            for (int s = 0; s < 6; s++) {
                int idx = base + s * (NCOMPUTE * 256);
                // conv_w: [l][row(128)][j(32)][2] -> g_wT[(l*32+j)*128+row]
                int l = idx / 4096, rem = idx & 4095, row = rem / 32, j = rem & 31;
                float2 v = ((const float2*)conv_w)[idx];
                g_wT[(l * 32 + j) * 128 + row] = v;
                // fc1_w: [k(128)][768] -> g_f1T[idx] with idx == (l*32+jj)*128+k
                int jj = rem >> 7, k = rem & 127;
                g_f1T[idx] = fc1_w[k * 768 + l * 32 + jj];
            }
        }
        __threadfence();
        __syncthreads();
        // generation barrier across the 64 compute blocks (replay-safe, monotonic)
        if (threadIdx.x == 0) {
            unsigned long long gen = atomicAdd(&g_ctr, 1ULL) / NCOMPUTE;
            unsigned long long target = (gen + 1ULL) * NCOMPUTE;
            while (atomicAdd(&g_ctr, 0ULL) < target) { }
        }
        __syncthreads();
        __threadfence();

        // ---- compute path: 1 warp = 1 batch element; lane = R index ----
        int warp = threadIdx.x >> 5;
        int lane = threadIdx.x & 31;
        int b    = blockIdx.x * 8 + warp;

        float h, c;
        {
            float ha = fc_h_b[lane], ca = fc_c_b[lane];
            #pragma unroll
            for (int i = 0; i < 9; i++) {
                float wh = fc_h_w[lane * 9 + i];
                float wc = fc_c_w[lane * 9 + i];
                float v  = (i == 0) ? x[b] : feat[b * 8 + i - 1];
                ha += wh * v; ca += wc * v;
            }
            h = tanhf(ha); c = tanhf(ca);
        }
        // h BEFORE layer 0 -> t=256 column of layer 0's queue rows
        out[BATCH + (size_t)((0 * BATCH + b) * RDIM + lane) * LOUT + 256] = h;

        float y0 = 0.f, y1 = 0.f, y2 = 0.f, y3 = 0.f;

        #pragma unroll 1
        for (int l = 0; l < NLAYERS; l++) {
            int dil = 1 << (l & 7);
            float p = __ldg(queues + (size_t)((l * BATCH + b) * RDIM + lane) * LQ + (LQ - dil));

            float a0 = __ldg(conv_b + l * 128 +  0 + lane);
            float a1 = __ldg(conv_b + l * 128 + 32 + lane);
            float a2 = __ldg(conv_b + l * 128 + 64 + lane);
            float a3 = __ldg(conv_b + l * 128 + 96 + lane);

            const float2* wp = g_wT + l * 32 * 128;
            #pragma unroll 8
            for (int j = 0; j < 32; j++) {
                float pj = __shfl_sync(FULLMASK, p, j);
                float hj = __shfl_sync(FULLMASK, h, j);
                float2 w0 = wp[j * 128 +  0 + lane];
                float2 w1 = wp[j * 128 + 32 + lane];
                float2 w2 = wp[j * 128 + 64 + lane];
                float2 w3 = wp[j * 128 + 96 + lane];
                a0 += w0.x * pj + w0.y * hj;
                a1 += w1.x * pj + w1.y * hj;
                a2 += w2.x * pj + w2.y * hj;
                a3 += w3.x * pj + w3.y * hj;
            }
            c = sigf(a0) * c + tanhf(a1) * sigf(a2);
            h = sigf(a3) * tanhf(c);

            if (l < NLAYERS - 1)
                out[BATCH + (size_t)(((l + 1) * BATCH + b) * RDIM + lane) * LOUT + 256] = h;

            const float* f1p = g_f1T + l * 32 * 128;
            #pragma unroll 8
            for (int j = 0; j < 32; j++) {
                float hj = __shfl_sync(FULLMASK, h, j);
                y0 += f1p[j * 128 +  0 + lane] * hj;
                y1 += f1p[j * 128 + 32 + lane] * hj;
                y2 += f1p[j * 128 + 64 + lane] * hj;
                y3 += f1p[j * 128 + 96 + lane] * hj;
            }
        }

        float sacc = fmaxf(y0 + fc1_b[ 0 + lane], 0.f) * fc2_w[ 0 + lane]
                   + fmaxf(y1 + fc1_b[32 + lane], 0.f) * fc2_w[32 + lane]
                   + fmaxf(y2 + fc1_b[64 + lane], 0.f) * fc2_w[64 + lane]
                   + fmaxf(y3 + fc1_b[96 + lane], 0.f) * fc2_w[96 + lane];
        #pragma unroll
        for (int off = 16; off > 0; off >>= 1)
            sacc += __shfl_xor_sync(FULLMASK, sacc, off);
        if (lane == 0) out[b] = sacc + fc2_b[0];
    } else {
        // ---- copy path: R8 champion loop, contiguous 32KB tiles, grid-stride ----
        float4* oq = (float4*)(out + BATCH);
        const unsigned nblk = NCOPYB;
        unsigned tid  = threadIdx.x;

        for (unsigned tile = (blockIdx.x - NCOMPUTE) * TILE4;
             tile < (unsigned)QOUT4;
             tile += nblk * TILE4) {
            unsigned idx[ILP];
            float4   v[ILP];
            bool     fast[ILP];
            #pragma unroll
            for (int k = 0; k < ILP; k++) {
                unsigned i4 = tile + (unsigned)k * 256u + tid;
                idx[k] = i4;
                fast[k] = false;
                {
                    unsigned e   = i4 * 4u;
                    unsigned row = e / 257u;
                    unsigned t   = e - row * 257u;
                    if (t < 253u) {
                        fast[k] = true;
                        const float* src = queues + (size_t)row * 256u + t;
                        v[k].x = __ldcs(src + 0);
                        v[k].y = __ldcs(src + 1);
                        v[k].z = __ldcs(src + 2);
                        v[k].w = __ldcs(src + 3);
                    }
                }
            }
            #pragma unroll
            for (int k = 0; k < ILP; k++) {
                if (fast[k]) {
                    __stcs(oq + idx[k], v[k]);
                } else {
                    // row-wrap / t==256 slow path (t==256 owned by compute warps)
                    unsigned e = idx[k] * 4u;
                    #pragma unroll
                    for (int j = 0; j < 4; j++) {
                        unsigned ee = e + (unsigned)j;
                        unsigned r2 = ee / 257u;
                        unsigned t2 = ee - r2 * 257u;
                        if (t2 < 256u) {
                            float val = __ldcs(queues + (size_t)r2 * 256u + t2);
                            __stcs(out + BATCH + ee, val);
                        }
                    }
                }
            }
        }
    }
}

extern "C" void kernel_launch(void* const* d_in, const int* in_sizes, int n_in,
                              void* d_out, int out_size) {
    const float* x      = (const float*)d_in[0];
    const float* feat   = (const float*)d_in[1];
    const float* queues = (const float*)d_in[2];
    const float* fc_h_w = (const float*)d_in[3];
    const float* fc_h_b = (const float*)d_in[4];
    const float* fc_c_w = (const float*)d_in[5];
    const float* fc_c_b = (const float*)d_in[6];
    const float* conv_w = (const float*)d_in[7];
    const float* conv_b = (const float*)d_in[8];
    const float* fc1_w  = (const float*)d_in[9];
    const float* fc1_b  = (const float*)d_in[10];
    const float* fc2_w  = (const float*)d_in[11];
    const float* fc2_b  = (const float*)d_in[12];
    float* out = (float*)d_out;

    main_kernel<<<NCOMPUTE + NCOPYB, 256>>>(x, feat, queues,
                                            fc_h_w, fc_h_b, fc_c_w, fc_c_b,
                                            conv_w, conv_b, fc1_w,
                                            fc1_b, fc2_w, fc2_b, out);
}

// round 11
// speedup vs baseline: 1.1770x; 1.0041x over previous
#include <cuda_runtime.h>
#include <stdint.h>

#define NLAYERS 24
#define BATCH   512
#define RDIM    32
#define LQ      256
#define LOUT    257
#define NROWS   (NLAYERS*BATCH*RDIM)      /* 393216 rows of 256 floats */
#define NSUPER  12288u                    /* 393216 / 32 rows per supertile */
#define NCOMPUTE 64                       /* 64 blocks x 8 warps = 512 batches */
#define NCOPYB   1984
#define FULLMASK 0xffffffffu

// ---------------- scratch (static device globals; no allocation) ----------------
__device__ float2 g_wT [NLAYERS*32*128];   // [l][j][row] -> (w_past, w_h)
__device__ float  g_f1T[NLAYERS*32*128];   // [l][j][k]

__device__ __forceinline__ float sigf(float v) { return 1.0f / (1.0f + __expf(-v)); }

// ---------------- K0: weight transposes for coalesced lane access ----------------
__global__ void prep_kernel(const float* __restrict__ conv_w,
                            const float* __restrict__ fc1_w) {
    int idx = blockIdx.x * blockDim.x + threadIdx.x;
    if (idx >= NLAYERS * 32 * 128) return;
    {
        // conv_w: [l][row(128)][j(32)][2]  (float2 index = (l*128+row)*32 + j)
        int l = idx / 4096, rem = idx & 4095, row = rem / 32, j = rem & 31;
        float2 v = ((const float2*)conv_w)[idx];
        g_wT[(l * 32 + j) * 128 + row] = v;
    }
    {
        // fc1_w: [k(128)][768];  dst [l][j][k], idx == (l*32+j)*128 + k
        int l = idx / 4096, rem = idx & 4095, j = rem >> 7, k = rem & 127;
        g_f1T[idx] = fc1_w[k * 768 + l * 32 + j];
        (void)l;
    }
}

// ---------------- K1: fused recurrence + row-identity queue copy ----------------
__global__ void __launch_bounds__(256, 4) main_kernel(
    const float* __restrict__ x,      const float* __restrict__ feat,
    const float* __restrict__ queues,
    const float* __restrict__ fc_h_w, const float* __restrict__ fc_h_b,
    const float* __restrict__ fc_c_w, const float* __restrict__ fc_c_b,
    const float* __restrict__ conv_b,
    const float* __restrict__ fc1_b,  const float* __restrict__ fc2_w,
    const float* __restrict__ fc2_b,
    float* __restrict__ out)
{
    if (blockIdx.x < NCOMPUTE) {
        // ---- compute path: 1 warp = 1 batch element; lane = R index ----
        int warp = threadIdx.x >> 5;
        int lane = threadIdx.x & 31;
        int b    = blockIdx.x * 8 + warp;

        float h, c;
        {
            float ha = fc_h_b[lane], ca = fc_c_b[lane];
            #pragma unroll
            for (int i = 0; i < 9; i++) {
                float wh = fc_h_w[lane * 9 + i];
                float wc = fc_c_w[lane * 9 + i];
                float v  = (i == 0) ? x[b] : feat[b * 8 + i - 1];
                ha += wh * v; ca += wc * v;
            }
            h = tanhf(ha); c = tanhf(ca);
        }
        // h BEFORE layer 0 -> t=256 column of layer 0's queue rows
        out[BATCH + (size_t)((0 * BATCH + b) * RDIM + lane) * LOUT + 256] = h;

        float y0 = 0.f, y1 = 0.f, y2 = 0.f, y3 = 0.f;

        #pragma unroll 1
        for (int l = 0; l < NLAYERS; l++) {
            int dil = 1 << (l & 7);
            float p = __ldg(queues + (size_t)((l * BATCH + b) * RDIM + lane) * LQ + (LQ - dil));

            float a0 = __ldg(conv_b + l * 128 +  0 + lane);
            float a1 = __ldg(conv_b + l * 128 + 32 + lane);
            float a2 = __ldg(conv_b + l * 128 + 64 + lane);
            float a3 = __ldg(conv_b + l * 128 + 96 + lane);

            const float2* wp = g_wT + l * 32 * 128;
            #pragma unroll 8
            for (int j = 0; j < 32; j++) {
                float pj = __shfl_sync(FULLMASK, p, j);
                float hj = __shfl_sync(FULLMASK, h, j);
                float2 w0 = wp[j * 128 +  0 + lane];
                float2 w1 = wp[j * 128 + 32 + lane];
                float2 w2 = wp[j * 128 + 64 + lane];
                float2 w3 = wp[j * 128 + 96 + lane];
                a0 += w0.x * pj + w0.y * hj;
                a1 += w1.x * pj + w1.y * hj;
                a2 += w2.x * pj + w2.y * hj;
                a3 += w3.x * pj + w3.y * hj;
            }
            c = sigf(a0) * c + tanhf(a1) * sigf(a2);
            h = sigf(a3) * tanhf(c);

            if (l < NLAYERS - 1)
                out[BATCH + (size_t)(((l + 1) * BATCH + b) * RDIM + lane) * LOUT + 256] = h;

            const float* f1p = g_f1T + l * 32 * 128;
            #pragma unroll 8
            for (int j = 0; j < 32; j++) {
                float hj = __shfl_sync(FULLMASK, h, j);
                y0 += f1p[j * 128 +  0 + lane] * hj;
                y1 += f1p[j * 128 + 32 + lane] * hj;
                y2 += f1p[j * 128 + 64 + lane] * hj;
                y3 += f1p[j * 128 + 96 + lane] * hj;
            }
        }

        float sacc = fmaxf(y0 + fc1_b[ 0 + lane], 0.f) * fc2_w[ 0 + lane]
                   + fmaxf(y1 + fc1_b[32 + lane], 0.f) * fc2_w[32 + lane]
                   + fmaxf(y2 + fc1_b[64 + lane], 0.f) * fc2_w[64 + lane]
                   + fmaxf(y3 + fc1_b[96 + lane], 0.f) * fc2_w[96 + lane];
        #pragma unroll
        for (int off = 16; off > 0; off >>= 1)
            sacc += __shfl_xor_sync(FULLMASK, sacc, off);
        if (lane == 0) out[b] = sacc + fc2_b[0];
    } else {
        // ---- copy path: ROW-IDENTITY. warp = row, lane+32k = t.
        //      out[512 + row*257 + t] = queues[row*256 + t], t in [0,256).
        //      Source 128B-coalesced & aligned; dest 128B-coalesced (<=12B skew,
        //      merged in L2). No divides, no boundaries, no smem. ----
        int warp = threadIdx.x >> 5;
        int lane = threadIdx.x & 31;

        for (unsigned st = blockIdx.x - NCOMPUTE; st < NSUPER; st += NCOPYB) {
            unsigned row0 = st * 32u + (unsigned)warp * 4u;
            #pragma unroll
            for (int g = 0; g < 4; g++) {
                unsigned row = row0 + (unsigned)g;
                const float* src = queues + (size_t)row * 256u + lane;
                float*       dst = out + BATCH + (size_t)row * 257u + lane;
                float v[8];
                #pragma unroll
                for (int k = 0; k < 8; k++) v[k] = __ldcs(src + 32 * k);
                #pragma unroll
                for (int k = 0; k < 8; k++) __stcs(dst + 32 * k, v[k]);
            }
        }
    }
}

extern "C" void kernel_launch(void* const* d_in, const int* in_sizes, int n_in,
                              void* d_out, int out_size) {
    const float* x      = (const float*)d_in[0];
    const float* feat   = (const float*)d_in[1];
    const float* queues = (const float*)d_in[2];
    const float* fc_h_w = (const float*)d_in[3];
    const float* fc_h_b = (const float*)d_in[4];
    const float* fc_c_w = (const float*)d_in[5];
    const float* fc_c_b = (const float*)d_in[6];
    const float* conv_w = (const float*)d_in[7];
    const float* conv_b = (const float*)d_in[8];
    const float* fc1_w  = (const float*)d_in[9];
    const float* fc1_b  = (const float*)d_in[10];
    const float* fc2_w  = (const float*)d_in[11];
    const float* fc2_b  = (const float*)d_in[12];
    float* out = (float*)d_out;

    prep_kernel<<<(NLAYERS * 32 * 128 + 255) / 256, 256>>>(conv_w, fc1_w);
    main_kernel<<<NCOMPUTE + NCOPYB, 256>>>(x, feat, queues,
                                            fc_h_w, fc_h_b, fc_c_w, fc_c_b,
                                            conv_b, fc1_b, fc2_w, fc2_b, out);
}